// round 14
// baseline (speedup 1.0000x reference)
#include <cuda_runtime.h>
#include <math.h>

// Problem constants
#define BS   8
#define C    256
#define H    64
#define W    64
#define NK   16
#define KQ   2304                 // C*9 (reduction length per out-channel)
#define P    589824               // C*C*9 (weights per expert / per aggregated sample)

// ---------------------------------------------------------------------------
// Device scratch (allocation-free rule: __device__ globals)
// ---------------------------------------------------------------------------
__device__ float g_att [BS * NK];          // softmax attention   [b][k]
__device__ float g_aggb[BS * C];           // aggregated bias     [b][o]
__device__ float g_aggw[(size_t)BS * P];   // aggregated weights  [b][o][ci][3][3]  (18.9 MB)

// ---------------------------------------------------------------------------
// Kernel 1: adaptive-pool 56->28, MLP 784->196(relu)->16, softmax(/30),
//           plus aggregated bias. One block per batch sample.
// ---------------------------------------------------------------------------
__global__ void attn_kernel(const float* __restrict__ sk,     // [8,1,56,56]
                            const float* __restrict__ w1,     // [196,784]
                            const float* __restrict__ w2,     // [16,196]
                            const float* __restrict__ bias)   // [16,256]
{
    const int b   = blockIdx.x;
    const int tid = threadIdx.x;

    __shared__ float pooled[784];
    __shared__ float hdn[196];
    __shared__ float att_s[NK];

    // 2x2 average pool 56x56 -> 28x28
    const float* skb = sk + b * 3136;
    for (int idx = tid; idx < 784; idx += 256) {
        int py = idx / 28, px = idx - py * 28;
        const float* p0 = skb + (2 * py) * 56 + 2 * px;
        pooled[idx] = 0.25f * (p0[0] + p0[1] + p0[56] + p0[57]);
    }
    __syncthreads();

    // hdn = relu(pooled @ w1^T)
    if (tid < 196) {
        const float* wr = w1 + tid * 784;
        float s = 0.f;
        #pragma unroll 4
        for (int i = 0; i < 784; ++i) s = fmaf(pooled[i], wr[i], s);
        hdn[tid] = fmaxf(s, 0.f);
    }
    __syncthreads();

    // logits/T
    if (tid < NK) {
        const float* wr = w2 + tid * 196;
        float s = 0.f;
        #pragma unroll 4
        for (int i = 0; i < 196; ++i) s = fmaf(hdn[i], wr[i], s);
        att_s[tid] = s * (1.0f / 30.0f);
    }
    __syncthreads();

    // softmax over 16 (serial, tiny)
    if (tid == 0) {
        float m = att_s[0];
        #pragma unroll
        for (int k = 1; k < NK; ++k) m = fmaxf(m, att_s[k]);
        float sum = 0.f;
        #pragma unroll
        for (int k = 0; k < NK; ++k) { att_s[k] = expf(att_s[k] - m); sum += att_s[k]; }
        float inv = 1.f / sum;
        #pragma unroll
        for (int k = 0; k < NK; ++k) { att_s[k] *= inv; g_att[b * NK + k] = att_s[k]; }
    }
    __syncthreads();

    // aggregated bias: aggb[b][o] = sum_k att[k] * bias[k][o]   (256 threads == C)
    {
        const int o = tid;
        float s = 0.f;
        #pragma unroll
        for (int k = 0; k < NK; ++k) s = fmaf(att_s[k], bias[k * C + o], s);
        g_aggb[b * C + o] = s;
    }
}

// ---------------------------------------------------------------------------
// Kernel 2: agg_w[b][p] = sum_k att[b][k] * weight[k][p]
// Streaming, fully coalesced. Grid covers P exactly.
// ---------------------------------------------------------------------------
__global__ void aggw_kernel(const float* __restrict__ weight)  // [16, P]
{
    __shared__ float att_s[BS * NK];
    if (threadIdx.x < BS * NK) att_s[threadIdx.x] = g_att[threadIdx.x];
    __syncthreads();

    const int p = blockIdx.x * 256 + threadIdx.x;
    float acc[BS];
    #pragma unroll
    for (int b = 0; b < BS; ++b) acc[b] = 0.f;

    #pragma unroll
    for (int k = 0; k < NK; ++k) {
        const float wv = weight[k * P + p];
        #pragma unroll
        for (int b = 0; b < BS; ++b) acc[b] = fmaf(att_s[b * NK + k], wv, acc[b]);
    }
    #pragma unroll
    for (int b = 0; b < BS; ++b) g_aggw[(size_t)b * P + p] = acc[b];
}

// ---------------------------------------------------------------------------
// Kernel 3: per-sample 3x3 SAME conv + bias + residual.
// Block: 64 out-channels x (8x8) pixel tile, 256 threads, thread-tile 4x4.
// K-loop: 8 input channels per iteration; x tile [8][10][11] (halo, pad 11),
// w tile transposed in smem [72][65] (stride 65 -> conflict-free).
// ---------------------------------------------------------------------------
__global__ void __launch_bounds__(256)
conv_kernel(const float* __restrict__ x, float* __restrict__ out)
{
    const int b     = blockIdx.z;
    const int obase = blockIdx.y * 64;
    const int tr0   = (blockIdx.x >> 3) * 8;   // tile row origin
    const int tc0   = (blockIdx.x & 7) * 8;    // tile col origin
    const int tid   = threadIdx.x;
    const int ty4   = (tid >> 4) * 4;          // out-channel sub-offset (0..60)
    const int tx    = tid & 15;
    const int pr    = tx >> 1;                 // pixel row in tile (0..7)
    const int pc    = (tx & 1) * 4;            // pixel col base in tile {0,4}

    __shared__ float xs[8 * 10 * 11];          // [c][rr][cc], row stride 11
    __shared__ float ws[72 * 65];              // [kk][o],     row stride 65

    float acc[4][4];
    #pragma unroll
    for (int i = 0; i < 4; ++i)
        #pragma unroll
        for (int j = 0; j < 4; ++j) acc[i][j] = 0.f;

    const float* xb = x + (size_t)b * C * H * W;
    const float* wb = g_aggw + (size_t)b * P + (size_t)obase * KQ;

    for (int cbase = 0; cbase < C; cbase += 8) {
        __syncthreads();

        // ---- load x tile [8 ch][10][10] with halo (zero padded) ----
        for (int l = tid; l < 800; l += 256) {
            int c   = l / 100;
            int rem = l - c * 100;
            int rr  = rem / 10;
            int cc  = rem - rr * 10;
            int gr  = tr0 - 1 + rr;
            int gc  = tc0 - 1 + cc;
            float v = 0.f;
            if ((unsigned)gr < 64u && (unsigned)gc < 64u)
                v = xb[(cbase + c) * 4096 + gr * 64 + gc];
            xs[c * 110 + rr * 11 + cc] = v;
        }

        // ---- load w tile: 64 o x 72 kk, stored transposed ws[kk][o] ----
        const float* wsrc = wb + cbase * 9;    // contiguous 72 floats per o
        #pragma unroll
        for (int it = 0; it < 18; ++it) {
            int l  = tid + it * 256;           // 18*256 == 4608 exactly
            int o  = l / 72;
            int kk = l - o * 72;
            ws[kk * 65 + o] = wsrc[o * KQ + kk];
        }
        __syncthreads();

        // ---- compute: 8 ch x 9 taps, 16 FMAs per (oc,pixel) per tap ----
        #pragma unroll 2
        for (int c = 0; c < 8; ++c) {
            #pragma unroll
            for (int r = 0; r < 3; ++r) {
                float xr[6];
                const float* xrow = &xs[c * 110 + (pr + r) * 11 + pc];
                #pragma unroll
                for (int j = 0; j < 6; ++j) xr[j] = xrow[j];
                #pragma unroll
                for (int s = 0; s < 3; ++s) {
                    const float* wv = &ws[(c * 9 + r * 3 + s) * 65 + ty4];
                    const float w0 = wv[0], w1 = wv[1], w2 = wv[2], w3 = wv[3];
                    #pragma unroll
                    for (int j = 0; j < 4; ++j) {
                        const float xv = xr[s + j];
                        acc[0][j] = fmaf(w0, xv, acc[0][j]);
                        acc[1][j] = fmaf(w1, xv, acc[1][j]);
                        acc[2][j] = fmaf(w2, xv, acc[2][j]);
                        acc[3][j] = fmaf(w3, xv, acc[3][j]);
                    }
                }
            }
        }
    }

    // ---- epilogue: + bias + residual, vectorized store ----
    const int row = tr0 + pr;
    const int col = tc0 + pc;
    #pragma unroll
    for (int oc = 0; oc < 4; ++oc) {
        const int o = obase + ty4 + oc;
        const float bo = g_aggb[b * C + o];
        const size_t base = ((size_t)(b * C + o) * 64 + row) * 64 + col;
        const float4 xin = *reinterpret_cast<const float4*>(x + base);
        float4 r;
        r.x = acc[oc][0] + bo + xin.x;
        r.y = acc[oc][1] + bo + xin.y;
        r.z = acc[oc][2] + bo + xin.z;
        r.w = acc[oc][3] + bo + xin.w;
        *reinterpret_cast<float4*>(out + base) = r;
    }
}

// ---------------------------------------------------------------------------
// Launch: three kernels on the default stream (graph-capturable, no syncs,
// no allocations). Stream order provides the inter-kernel dependencies.
// Input order per metadata: x, scene_knowledge, weight, bias, att_w1, att_w2.
// ---------------------------------------------------------------------------
extern "C" void kernel_launch(void* const* d_in, const int* in_sizes, int n_in,
                              void* d_out, int out_size)
{
    const float* x    = (const float*)d_in[0];
    const float* sk   = (const float*)d_in[1];
    const float* wt   = (const float*)d_in[2];
    const float* bias = (const float*)d_in[3];
    const float* w1   = (const float*)d_in[4];
    const float* w2   = (const float*)d_in[5];
    float* out = (float*)d_out;

    attn_kernel<<<BS, 256>>>(sk, w1, w2, bias);
    aggw_kernel<<<P / 256, 256>>>(wt);
    conv_kernel<<<dim3(64, C / 64, BS), 256>>>(x, out);
}

// round 15
// speedup vs baseline: 1.0045x; 1.0045x over previous
#include <cuda_runtime.h>
#include <math.h>

// Problem constants
#define BS   8
#define C    256
#define H    64
#define W    64
#define NK   16
#define KQ   2304                 // C*9 (reduction length per out-channel)
#define P    589824               // C*C*9 (weights per expert / per aggregated sample)

// ---------------------------------------------------------------------------
// Device scratch (allocation-free rule: __device__ globals)
// ---------------------------------------------------------------------------
__device__ float g_att [BS * NK];          // softmax attention   [b][k]
__device__ float g_aggb[BS * C];           // aggregated bias     [b][o]
__device__ float g_aggw[(size_t)BS * P];   // aggregated weights  [b][o][ci][3][3]  (18.9 MB)

// ---------------------------------------------------------------------------
// Kernel 1: adaptive-pool 56->28, MLP 784->196(relu)->16, softmax(/30),
//           plus aggregated bias. One block per batch sample.
// ---------------------------------------------------------------------------
__global__ void attn_kernel(const float* __restrict__ sk,     // [8,1,56,56]
                            const float* __restrict__ w1,     // [196,784]
                            const float* __restrict__ w2,     // [16,196]
                            const float* __restrict__ bias)   // [16,256]
{
    const int b   = blockIdx.x;
    const int tid = threadIdx.x;

    __shared__ float pooled[784];
    __shared__ float hdn[196];
    __shared__ float att_s[NK];

    // 2x2 average pool 56x56 -> 28x28
    const float* skb = sk + b * 3136;
    for (int idx = tid; idx < 784; idx += 256) {
        int py = idx / 28, px = idx - py * 28;
        const float* p0 = skb + (2 * py) * 56 + 2 * px;
        pooled[idx] = 0.25f * (p0[0] + p0[1] + p0[56] + p0[57]);
    }
    __syncthreads();

    // hdn = relu(pooled @ w1^T)
    if (tid < 196) {
        const float* wr = w1 + tid * 784;
        float s = 0.f;
        #pragma unroll 4
        for (int i = 0; i < 784; ++i) s = fmaf(pooled[i], wr[i], s);
        hdn[tid] = fmaxf(s, 0.f);
    }
    __syncthreads();

    // logits/T
    if (tid < NK) {
        const float* wr = w2 + tid * 196;
        float s = 0.f;
        #pragma unroll 4
        for (int i = 0; i < 196; ++i) s = fmaf(hdn[i], wr[i], s);
        att_s[tid] = s * (1.0f / 30.0f);
    }
    __syncthreads();

    // softmax over 16 (serial, tiny)
    if (tid == 0) {
        float m = att_s[0];
        #pragma unroll
        for (int k = 1; k < NK; ++k) m = fmaxf(m, att_s[k]);
        float sum = 0.f;
        #pragma unroll
        for (int k = 0; k < NK; ++k) { att_s[k] = expf(att_s[k] - m); sum += att_s[k]; }
        float inv = 1.f / sum;
        #pragma unroll
        for (int k = 0; k < NK; ++k) { att_s[k] *= inv; g_att[b * NK + k] = att_s[k]; }
    }
    __syncthreads();

    // aggregated bias: aggb[b][o] = sum_k att[k] * bias[k][o]   (256 threads == C)
    {
        const int o = tid;
        float s = 0.f;
        #pragma unroll
        for (int k = 0; k < NK; ++k) s = fmaf(att_s[k], bias[k * C + o], s);
        g_aggb[b * C + o] = s;
    }
}

// ---------------------------------------------------------------------------
// Kernel 2: agg_w[b][p] = sum_k att[b][k] * weight[k][p]
// Streaming, fully coalesced. Grid covers P exactly.
// ---------------------------------------------------------------------------
__global__ void aggw_kernel(const float* __restrict__ weight)  // [16, P]
{
    __shared__ float att_s[BS * NK];
    if (threadIdx.x < BS * NK) att_s[threadIdx.x] = g_att[threadIdx.x];
    __syncthreads();

    const int p = blockIdx.x * 256 + threadIdx.x;
    float acc[BS];
    #pragma unroll
    for (int b = 0; b < BS; ++b) acc[b] = 0.f;

    #pragma unroll
    for (int k = 0; k < NK; ++k) {
        const float wv = weight[k * P + p];
        #pragma unroll
        for (int b = 0; b < BS; ++b) acc[b] = fmaf(att_s[b * NK + k], wv, acc[b]);
    }
    #pragma unroll
    for (int b = 0; b < BS; ++b) g_aggw[(size_t)b * P + p] = acc[b];
}

// ---------------------------------------------------------------------------
// Kernel 3: per-sample 3x3 SAME conv + bias + residual.
// Block: 64 out-channels x (8x8) pixel tile, 256 threads, thread-tile 4x4.
// K-loop: 8 input channels per iteration; x tile [8][10][11] (halo, pad 11),
// w tile transposed in smem [72][65] (stride 65 -> conflict-free).
// ---------------------------------------------------------------------------
__global__ void __launch_bounds__(256)
conv_kernel(const float* __restrict__ x, float* __restrict__ out)
{
    const int b     = blockIdx.z;
    const int obase = blockIdx.y * 64;
    const int tr0   = (blockIdx.x >> 3) * 8;   // tile row origin
    const int tc0   = (blockIdx.x & 7) * 8;    // tile col origin
    const int tid   = threadIdx.x;
    const int ty4   = (tid >> 4) * 4;          // out-channel sub-offset (0..60)
    const int tx    = tid & 15;
    const int pr    = tx >> 1;                 // pixel row in tile (0..7)
    const int pc    = (tx & 1) * 4;            // pixel col base in tile {0,4}

    __shared__ float xs[8 * 10 * 11];          // [c][rr][cc], row stride 11
    __shared__ float ws[72 * 65];              // [kk][o],     row stride 65

    float acc[4][4];
    #pragma unroll
    for (int i = 0; i < 4; ++i)
        #pragma unroll
        for (int j = 0; j < 4; ++j) acc[i][j] = 0.f;

    const float* xb = x + (size_t)b * C * H * W;
    const float* wb = g_aggw + (size_t)b * P + (size_t)obase * KQ;

    for (int cbase = 0; cbase < C; cbase += 8) {
        __syncthreads();

        // ---- load x tile [8 ch][10][10] with halo (zero padded) ----
        for (int l = tid; l < 800; l += 256) {
            int c   = l / 100;
            int rem = l - c * 100;
            int rr  = rem / 10;
            int cc  = rem - rr * 10;
            int gr  = tr0 - 1 + rr;
            int gc  = tc0 - 1 + cc;
            float v = 0.f;
            if ((unsigned)gr < 64u && (unsigned)gc < 64u)
                v = xb[(cbase + c) * 4096 + gr * 64 + gc];
            xs[c * 110 + rr * 11 + cc] = v;
        }

        // ---- load w tile: 64 o x 72 kk, stored transposed ws[kk][o] ----
        const float* wsrc = wb + cbase * 9;    // contiguous 72 floats per o
        #pragma unroll
        for (int it = 0; it < 18; ++it) {
            int l  = tid + it * 256;           // 18*256 == 4608 exactly
            int o  = l / 72;
            int kk = l - o * 72;
            ws[kk * 65 + o] = wsrc[o * KQ + kk];
        }
        __syncthreads();

        // ---- compute: 8 ch x 9 taps, 16 FMAs per (oc,pixel) per tap ----
        #pragma unroll 2
        for (int c = 0; c < 8; ++c) {
            #pragma unroll
            for (int r = 0; r < 3; ++r) {
                float xr[6];
                const float* xrow = &xs[c * 110 + (pr + r) * 11 + pc];
                #pragma unroll
                for (int j = 0; j < 6; ++j) xr[j] = xrow[j];
                #pragma unroll
                for (int s = 0; s < 3; ++s) {
                    const float* wv = &ws[(c * 9 + r * 3 + s) * 65 + ty4];
                    const float w0 = wv[0], w1 = wv[1], w2 = wv[2], w3 = wv[3];
                    #pragma unroll
                    for (int j = 0; j < 4; ++j) {
                        const float xv = xr[s + j];
                        acc[0][j] = fmaf(w0, xv, acc[0][j]);
                        acc[1][j] = fmaf(w1, xv, acc[1][j]);
                        acc[2][j] = fmaf(w2, xv, acc[2][j]);
                        acc[3][j] = fmaf(w3, xv, acc[3][j]);
                    }
                }
            }
        }
    }

    // ---- epilogue: + bias + residual, vectorized store ----
    const int row = tr0 + pr;
    const int col = tc0 + pc;
    #pragma unroll
    for (int oc = 0; oc < 4; ++oc) {
        const int o = obase + ty4 + oc;
        const float bo = g_aggb[b * C + o];
        const size_t base = ((size_t)(b * C + o) * 64 + row) * 64 + col;
        const float4 xin = *reinterpret_cast<const float4*>(x + base);
        float4 r;
        r.x = acc[oc][0] + bo + xin.x;
        r.y = acc[oc][1] + bo + xin.y;
        r.z = acc[oc][2] + bo + xin.z;
        r.w = acc[oc][3] + bo + xin.w;
        *reinterpret_cast<float4*>(out + base) = r;
    }
}

// ---------------------------------------------------------------------------
// Launch: three kernels on the default stream (graph-capturable, no syncs,
// no allocations). Stream order provides the inter-kernel dependencies.
// Input order per metadata: x, scene_knowledge, weight, bias, att_w1, att_w2.
// ---------------------------------------------------------------------------
extern "C" void kernel_launch(void* const* d_in, const int* in_sizes, int n_in,
                              void* d_out, int out_size)
{
    const float* x    = (const float*)d_in[0];
    const float* sk   = (const float*)d_in[1];
    const float* wt   = (const float*)d_in[2];
    const float* bias = (const float*)d_in[3];
    const float* w1   = (const float*)d_in[4];
    const float* w2   = (const float*)d_in[5];
    float* out = (float*)d_out;

    attn_kernel<<<BS, 256>>>(sk, w1, w2, bias);
    aggw_kernel<<<P / 256, 256>>>(wt);
    conv_kernel<<<dim3(64, C / 64, BS), 256>>>(x, out);
}